// round 5
// baseline (speedup 1.0000x reference)
#include <cuda_runtime.h>
#include <cuda_bf16.h>

typedef unsigned long long u64;

// Problem shapes
#define B_   1024
#define L_   200
#define DIM_ 100
#define NP   128               // padded N
#define KSPLIT 32
#define KCHUNK (B_ / KSPLIT)   // 32

// Scratch (allocation-free: __device__ globals)
__device__ __align__(256) float g_rel[B_ * NP];                 // mean-pooled, padded
__device__ __align__(256) float g_tmp[B_ * NP];                 // A @ rel
__device__ __align__(256) float g_part[KSPLIT * B_ * NP];       // split-K partials

// ---------------------------------------------------------------------------
// packed f32x2 helpers (sm_103a)
// ---------------------------------------------------------------------------
__device__ __forceinline__ void fma2(u64& d, u64 a, u64 b) {
    asm("fma.rn.f32x2 %0, %1, %2, %0;" : "+l"(d) : "l"(a), "l"(b));
}
__device__ __forceinline__ u64 pack2(float x) {
    u64 r;
    asm("mov.b64 %0, {%1, %1};" : "=l"(r) : "f"(x));
    return r;
}
__device__ __forceinline__ void unpack2(u64 v, float& lo, float& hi) {
    asm("mov.b64 {%0, %1}, %2;" : "=f"(lo), "=f"(hi) : "l"(v));
}

// ---------------------------------------------------------------------------
// Kernel 1: gather + mean-pool.  rel[b][t] = (1/len[b]) * sum_l emb[items[b,l]][t]
// 256 threads: warp w handles rows l in [w*25, w*25+25); lanes 0..24 each own
// one float4 column segment (25*4 = 100). emb rows are 400B -> 16B aligned.
// ---------------------------------------------------------------------------
__global__ __launch_bounds__(256) void gather_kernel(const float* __restrict__ emb,
                                                     const int* __restrict__ items,
                                                     const float* __restrict__ slen) {
    int b = blockIdx.x;
    int t = threadIdx.x;
    int w = t >> 5;              // warp 0..7
    int c = t & 31;              // lane

    __shared__ int sidx[L_];
    __shared__ float spart[8][DIM_];

    for (int l = t; l < L_; l += 256) sidx[l] = items[b * L_ + l];
    __syncthreads();

    float4 acc = make_float4(0.f, 0.f, 0.f, 0.f);
    if (c < 25) {
        int l0 = w * 25;
        #pragma unroll 5
        for (int l = l0; l < l0 + 25; l++) {
            int j = sidx[l];
            if (j > 0) {
                float4 v = *(const float4*)&emb[(long long)(j - 1) * DIM_ + c * 4];
                acc.x += v.x; acc.y += v.y; acc.z += v.z; acc.w += v.w;
            }
        }
        spart[w][c * 4 + 0] = acc.x;
        spart[w][c * 4 + 1] = acc.y;
        spart[w][c * 4 + 2] = acc.z;
        spart[w][c * 4 + 3] = acc.w;
    }
    __syncthreads();

    if (t < NP) {
        float s = 0.f;
        if (t < DIM_) {
            #pragma unroll
            for (int ww = 0; ww < 8; ww++) s += spart[ww][t];
            s *= 1.f / slen[b];
        }
        g_rel[b * NP + t] = s;
    }
}

// ---------------------------------------------------------------------------
// Kernel 2: split-K SGEMM with packed fma.rn.f32x2.
// BM=64, BN=128, KCHUNK=BK=32, grid (16,32)=512 blocks, 256 threads.
// Single K block: load whole 64x32 A tile + 32x128 B tile, one sync, compute.
// warp ty owns rows [ty*8, ty*8+8) (as 4 m-pairs), lane tx owns cols [tx*4,+4).
// ---------------------------------------------------------------------------
__global__ __launch_bounds__(256, 3) void gemm_splitk(const float* __restrict__ A,
                                                      int selB) {
    const float* __restrict__ Bm = selB ? g_tmp : g_rel;
    __shared__ float As[KCHUNK][64];     // [k][m], m contiguous -> free m-pairs
    __shared__ float Bs[KCHUNK][NP];

    int tid = threadIdx.x;
    int tx = tid & 31;           // lane
    int ty = tid >> 5;           // warp 0..7
    int m0 = blockIdx.x * 64;
    int kbase = blockIdx.y * KCHUNK;

    // --- load A tile (64 x 32): thread owns row lm, k range [lk, lk+8) ---
    {
        int lm = tid >> 2;               // 0..63
        int lk = (tid & 3) * 8;          // 0,8,16,24
        const float* Arow = &A[(long long)(m0 + lm) * B_ + kbase + lk];
        float4 v0 = *(const float4*)&Arow[0];
        float4 v1 = *(const float4*)&Arow[4];
        As[lk + 0][lm] = v0.x; As[lk + 1][lm] = v0.y;
        As[lk + 2][lm] = v0.z; As[lk + 3][lm] = v0.w;
        As[lk + 4][lm] = v1.x; As[lk + 5][lm] = v1.y;
        As[lk + 6][lm] = v1.z; As[lk + 7][lm] = v1.w;
    }
    // --- load B tile (32 x 128): thread owns rows br+{0,8,16,24}, col chunk ---
    {
        int br  = tid >> 5;              // 0..7
        int bc4 = (tid & 31) * 4;        // 0..124
        #pragma unroll
        for (int r = 0; r < 4; r++)
            *(float4*)&Bs[br + r * 8][bc4] =
                *(const float4*)&Bm[(kbase + br + r * 8) * NP + bc4];
    }
    __syncthreads();

    u64 acc2[4][4];              // [m-pair][n], pair = rows (2*i2, 2*i2+1)
    #pragma unroll
    for (int i = 0; i < 4; i++)
        #pragma unroll
        for (int j = 0; j < 4; j++) acc2[i][j] = 0ULL;

    #pragma unroll
    for (int k = 0; k < KCHUNK; k++) {
        ulonglong2 p0 = *(const ulonglong2*)&As[k][ty * 8];      // (m0,m1),(m2,m3)
        ulonglong2 p1 = *(const ulonglong2*)&As[k][ty * 8 + 4];  // (m4,m5),(m6,m7)
        float4 bv = *(const float4*)&Bs[k][tx * 4];
        u64 a2[4] = {p0.x, p0.y, p1.x, p1.y};
        u64 b2[4] = {pack2(bv.x), pack2(bv.y), pack2(bv.z), pack2(bv.w)};
        #pragma unroll
        for (int i = 0; i < 4; i++)
            #pragma unroll
            for (int j = 0; j < 4; j++)
                fma2(acc2[i][j], a2[i], b2[j]);
    }

    // unpack + write partials
    float* P = g_part + (long long)blockIdx.y * (B_ * NP);
    #pragma unroll
    for (int i2 = 0; i2 < 4; i2++) {
        float r0[4], r1[4];
        #pragma unroll
        for (int j = 0; j < 4; j++) unpack2(acc2[i2][j], r0[j], r1[j]);
        int m = m0 + ty * 8 + i2 * 2;
        *(float4*)&P[(m + 0) * NP + tx * 4] = make_float4(r0[0], r0[1], r0[2], r0[3]);
        *(float4*)&P[(m + 1) * NP + tx * 4] = make_float4(r1[0], r1[1], r1[2], r1[3]);
    }
}

// ---------------------------------------------------------------------------
// Kernel 3: reduce split-K partials into g_tmp (float4 vectorized)
// ---------------------------------------------------------------------------
__global__ void reduce_kernel() {
    int i = (blockIdx.x * 256 + threadIdx.x) * 4;   // 0 .. 131068
    float4 s = make_float4(0.f, 0.f, 0.f, 0.f);
    #pragma unroll
    for (int c = 0; c < KSPLIT; c++) {
        float4 v = *(const float4*)&g_part[c * (B_ * NP) + i];
        s.x += v.x; s.y += v.y; s.z += v.z; s.w += v.w;
    }
    *(float4*)&g_tmp[i] = s;
}

// ---------------------------------------------------------------------------
// Kernel 4: fused split-K reduce + SELU + L2 row-normalize -> out [1024,100]
// ---------------------------------------------------------------------------
__global__ void epilogue_kernel(float* __restrict__ out) {
    int b = blockIdx.x;
    int t = threadIdx.x;

    float s = 0.f;
    #pragma unroll
    for (int c = 0; c < KSPLIT; c++) s += g_part[c * (B_ * NP) + b * NP + t];

    const float kScale = 1.0507009873554804934193349852946f;
    const float kAlpha = 1.6732632423543772848170429916717f;
    float cv = kScale * (s > 0.f ? s : kAlpha * (expf(s) - 1.f));

    float v = (t < DIM_) ? cv * cv : 0.f;
    #pragma unroll
    for (int o = 16; o > 0; o >>= 1) v += __shfl_xor_sync(0xFFFFFFFFu, v, o);
    __shared__ float red[4];
    if ((t & 31) == 0) red[t >> 5] = v;
    __syncthreads();
    float nrm = rsqrtf(red[0] + red[1] + red[2] + red[3]);

    if (t < DIM_) out[b * DIM_ + t] = cv * nrm;
}

// ---------------------------------------------------------------------------
extern "C" void kernel_launch(void* const* d_in, const int* in_sizes, int n_in,
                              void* d_out, int out_size) {
    const float* emb   = (const float*)d_in[0];      // [50000,100] f32
    const int*   items = (const int*)d_in[1];        // [1024,200] int32
    const float* A     = (const float*)d_in[2];      // [1024,1024] f32
    const float* D     = (const float*)d_in[3];      // [1024,1024] f32
    const float* slen  = (const float*)d_in[4];      // [1024,1] f32
    float*       out   = (float*)d_out;              // [1024,100] f32

    gather_kernel<<<B_, 256>>>(emb, items, slen);

    dim3 ggrid(B_ / 64, KSPLIT);                  // (16,32) = 512 blocks
    gemm_splitk<<<ggrid, 256>>>(A, /*selB=*/0);   // partials of A @ rel
    reduce_kernel<<<(B_ * NP) / 1024, 256>>>();   // g_tmp = A @ rel
    gemm_splitk<<<ggrid, 256>>>(D, /*selB=*/1);   // partials of D @ (A @ rel)
    epilogue_kernel<<<B_, 128>>>(out);            // reduce + selu + L2 norm
}